// round 8
// baseline (speedup 1.0000x reference)
#include <cuda_runtime.h>
#include <cuda_bf16.h>
#include <cstdint>

// Problem constants
#define BDIM 2
#define VDIM 8
#define PDIM 4096
#define DDIM 1024
#define NREF 256
#define EN   16384
#define NCAND 16

// Scratch (device globals: allocation-free)
__device__ float g_sim[BDIM * NREF * EN];        // 33.5 MB
__device__ int   g_topk[BDIM * NREF * 4];
__device__ float g_accum[3];
__device__ unsigned g_done;

__constant__ int c_ST[3] = {2, 4, 6};   // SHARED_TEACHER
__constant__ int c_SS[3] = {1, 2, 3};   // SHARED_STUDENT

__device__ __forceinline__ void ins4(float x, int e, float* v, int* id) {
    if (x <= v[3]) return;
    v[3] = x; id[3] = e;
    #pragma unroll
    for (int j = 3; j >= 1; j--) {
        if (v[j] > v[j - 1]) {
            float tv = v[j]; v[j] = v[j - 1]; v[j - 1] = tv;
            int ti = id[j]; id[j] = id[j - 1]; id[j - 1] = ti;
        }
    }
}

__device__ __forceinline__ void ins16(float x, int e, float* v, int* id) {
    if (x <= v[15]) return;
    v[15] = x; id[15] = e;
    #pragma unroll
    for (int j = 15; j >= 1; j--) {
        if (v[j] > v[j - 1]) {
            float tv = v[j]; v[j] = v[j - 1]; v[j - 1] = tv;
            int ti = id[j]; id[j] = id[j - 1]; id[j - 1] = ti;
        }
    }
}

// pack 4 f32 -> 4 e4m3 bytes (byte0 = a, byte1 = b, byte2 = c, byte3 = d)
__device__ __forceinline__ uint32_t pack4_e4m3(float a, float b, float c, float d) {
    uint16_t lo, hi;
    asm("cvt.rn.satfinite.e4m3x2.f32 %0, %1, %2;" : "=h"(lo) : "f"(b), "f"(a));
    asm("cvt.rn.satfinite.e4m3x2.f32 %0, %1, %2;" : "=h"(hi) : "f"(d), "f"(c));
    return (uint32_t)lo | ((uint32_t)hi << 16);
}

// ---------------------------------------------------------------------------
// K1: sim GEMM via FP8 mma.sync (e4m3 x e4m3 -> fp32), fused f32->fp8
//     convert + fused exact f32 B-row norms. 128x128 CTA tile, BK=64 elems,
//     512 threads, warp tile 32x32 (m16n8k32 fragments).
// ---------------------------------------------------------------------------
#define GBK 64
#define SROWB 80   // bytes per smem row: 64 data + 16 pad

__global__ void __launch_bounds__(512, 1)
k_gemm(const float* __restrict__ teacher, const int* __restrict__ ref_perm) {
    __shared__ __align__(16) uint8_t As[128][SROWB];
    __shared__ __align__(16) uint8_t Bs[128][SROWB];
    __shared__ float s_inv[128];

    const int b     = blockIdx.z;
    const int rbase = blockIdx.y * 128;
    const int ebase = blockIdx.x * 128;
    const int tid   = threadIdx.x;
    const int lane  = tid & 31;
    const int wid   = tid >> 5;          // 0..15
    const int wm    = (wid >> 2) * 32;
    const int wn    = (wid & 3) * 32;

    // loaders: thread t -> row t>>2, 16-element segment (t&3)*16
    const int lrow = tid >> 2;
    const int lseg = (tid & 3) * 16;

    const float* aptr = teacher + ((size_t)(b * VDIM) * PDIM + ref_perm[rbase + lrow]) * DDIM + lseg;
    const int v = 2 * (ebase >> 12) + 1;           // EXTRA_FRAMES {1,3,5,7}
    const int p = (ebase & (PDIM - 1)) + lrow;
    const float* bptr = teacher + ((size_t)(b * VDIM + v) * PDIM + p) * DDIM + lseg;

    float acc[2][4][4];
    #pragma unroll
    for (int i = 0; i < 2; i++)
        #pragma unroll
        for (int j = 0; j < 4; j++)
            #pragma unroll
            for (int k = 0; k < 4; k++) acc[i][j][k] = 0.f;

    uint4 pfa, pfb;
    float ssq = 0.f;

    // ldmatrix lane addressing: row xr in [0,16), 16B-half select xkB
    const int xr  = (lane & 7) + ((lane >> 3) & 1) * 8;
    const int xkB = (lane >> 4) * 16;
    uint32_t a_base[2], b_base[2];
    #pragma unroll
    for (int mi = 0; mi < 2; mi++)
        a_base[mi] = (uint32_t)__cvta_generic_to_shared(&As[wm + mi * 16 + xr][xkB]);
    #pragma unroll
    for (int nj = 0; nj < 2; nj++)
        b_base[nj] = (uint32_t)__cvta_generic_to_shared(&Bs[wn + nj * 16 + xr][xkB]);

    // initial prefetch (kt = 0): 16 A floats + 16 B floats -> fp8
    {
        float4 a0 = *(const float4*)(aptr);
        float4 a1 = *(const float4*)(aptr + 4);
        float4 a2 = *(const float4*)(aptr + 8);
        float4 a3 = *(const float4*)(aptr + 12);
        float4 b0 = *(const float4*)(bptr);
        float4 b1 = *(const float4*)(bptr + 4);
        float4 b2 = *(const float4*)(bptr + 8);
        float4 b3 = *(const float4*)(bptr + 12);
        ssq += b0.x*b0.x + b0.y*b0.y + b0.z*b0.z + b0.w*b0.w
             + b1.x*b1.x + b1.y*b1.y + b1.z*b1.z + b1.w*b1.w
             + b2.x*b2.x + b2.y*b2.y + b2.z*b2.z + b2.w*b2.w
             + b3.x*b3.x + b3.y*b3.y + b3.z*b3.z + b3.w*b3.w;
        pfa.x = pack4_e4m3(a0.x, a0.y, a0.z, a0.w);
        pfa.y = pack4_e4m3(a1.x, a1.y, a1.z, a1.w);
        pfa.z = pack4_e4m3(a2.x, a2.y, a2.z, a2.w);
        pfa.w = pack4_e4m3(a3.x, a3.y, a3.z, a3.w);
        pfb.x = pack4_e4m3(b0.x, b0.y, b0.z, b0.w);
        pfb.y = pack4_e4m3(b1.x, b1.y, b1.z, b1.w);
        pfb.z = pack4_e4m3(b2.x, b2.y, b2.z, b2.w);
        pfb.w = pack4_e4m3(b3.x, b3.y, b3.z, b3.w);
    }

    for (int kt = 0; kt < DDIM / GBK; kt++) {
        *(uint4*)&As[lrow][lseg] = pfa;
        *(uint4*)&Bs[lrow][lseg] = pfb;
        __syncthreads();

        if (kt + 1 < DDIM / GBK) {
            const float* ap = aptr + (kt + 1) * GBK;
            const float* bp = bptr + (kt + 1) * GBK;
            float4 a0 = *(const float4*)(ap);
            float4 a1 = *(const float4*)(ap + 4);
            float4 a2 = *(const float4*)(ap + 8);
            float4 a3 = *(const float4*)(ap + 12);
            float4 b0 = *(const float4*)(bp);
            float4 b1 = *(const float4*)(bp + 4);
            float4 b2 = *(const float4*)(bp + 8);
            float4 b3 = *(const float4*)(bp + 12);
            ssq += b0.x*b0.x + b0.y*b0.y + b0.z*b0.z + b0.w*b0.w
                 + b1.x*b1.x + b1.y*b1.y + b1.z*b1.z + b1.w*b1.w
                 + b2.x*b2.x + b2.y*b2.y + b2.z*b2.z + b2.w*b2.w
                 + b3.x*b3.x + b3.y*b3.y + b3.z*b3.z + b3.w*b3.w;
            pfa.x = pack4_e4m3(a0.x, a0.y, a0.z, a0.w);
            pfa.y = pack4_e4m3(a1.x, a1.y, a1.z, a1.w);
            pfa.z = pack4_e4m3(a2.x, a2.y, a2.z, a2.w);
            pfa.w = pack4_e4m3(a3.x, a3.y, a3.z, a3.w);
            pfb.x = pack4_e4m3(b0.x, b0.y, b0.z, b0.w);
            pfb.y = pack4_e4m3(b1.x, b1.y, b1.z, b1.w);
            pfb.z = pack4_e4m3(b2.x, b2.y, b2.z, b2.w);
            pfb.w = pack4_e4m3(b3.x, b3.y, b3.z, b3.w);
        }

        // 2 k-steps of 32 fp8 each
        #pragma unroll
        for (int ks = 0; ks < GBK; ks += 32) {
            uint32_t af[2][4], bf[2][4];
            #pragma unroll
            for (int mi = 0; mi < 2; mi++) {
                asm volatile("ldmatrix.sync.aligned.m8n8.x4.shared.b16 {%0,%1,%2,%3}, [%4];"
                    : "=r"(af[mi][0]), "=r"(af[mi][1]), "=r"(af[mi][2]), "=r"(af[mi][3])
                    : "r"(a_base[mi] + ks));
            }
            #pragma unroll
            for (int nj = 0; nj < 2; nj++) {
                asm volatile("ldmatrix.sync.aligned.m8n8.x4.shared.b16 {%0,%1,%2,%3}, [%4];"
                    : "=r"(bf[nj][0]), "=r"(bf[nj][1]), "=r"(bf[nj][2]), "=r"(bf[nj][3])
                    : "r"(b_base[nj] + ks));
            }
            #pragma unroll
            for (int mi = 0; mi < 2; mi++) {
                #pragma unroll
                for (int nj = 0; nj < 4; nj++) {
                    uint32_t bb0 = bf[nj >> 1][nj & 1];
                    uint32_t bb1 = bf[nj >> 1][(nj & 1) + 2];
                    asm volatile(
                        "mma.sync.aligned.m16n8k32.row.col.f32.e4m3.e4m3.f32 "
                        "{%0,%1,%2,%3}, {%4,%5,%6,%7}, {%8,%9}, {%0,%1,%2,%3};"
                        : "+f"(acc[mi][nj][0]), "+f"(acc[mi][nj][1]),
                          "+f"(acc[mi][nj][2]), "+f"(acc[mi][nj][3])
                        : "r"(af[mi][0]), "r"(af[mi][1]), "r"(af[mi][2]), "r"(af[mi][3]),
                          "r"(bb0), "r"(bb1));
                }
            }
        }
        __syncthreads();
    }

    // B-row inverse norms (exact, from f32): 4 threads per row
    ssq += __shfl_xor_sync(0xffffffffu, ssq, 1);
    ssq += __shfl_xor_sync(0xffffffffu, ssq, 2);
    if ((tid & 3) == 0) s_inv[lrow] = 1.0f / fmaxf(sqrtf(ssq), 1e-12f);
    __syncthreads();

    // epilogue: scale by inv_norm[e], write sim
    #pragma unroll
    for (int mi = 0; mi < 2; mi++) {
        int r = rbase + wm + mi * 16 + (lane >> 2);
        float* orow = g_sim + ((size_t)(b * NREF + r)) * EN + ebase;
        #pragma unroll
        for (int nj = 0; nj < 4; nj++) {
            int c = wn + nj * 8 + (lane & 3) * 2;
            float2 w0 = make_float2(acc[mi][nj][0] * s_inv[c], acc[mi][nj][1] * s_inv[c + 1]);
            float2 w1 = make_float2(acc[mi][nj][2] * s_inv[c], acc[mi][nj][3] * s_inv[c + 1]);
            *(float2*)(orow + c)          = w0;
            *(float2*)(orow + 8 * EN + c) = w1;
        }
    }
}

// ---------------------------------------------------------------------------
// K2: per (b,r): top-16 candidates from fp8 sims, then exact fp32 re-rank
//     -> exact top-4 indices. 512 threads; warp w handles candidate w.
// ---------------------------------------------------------------------------
__global__ void __launch_bounds__(512)
k_select(const float* __restrict__ teacher, const int* __restrict__ ref_perm) {
    int r = blockIdx.x, b = blockIdx.y, tid = threadIdx.x;
    int w = tid >> 5, lane = tid & 31;
    const float* row = g_sim + ((size_t)(b * NREF + r)) * EN;

    if (r == 0 && b == 0 && tid < 3) g_accum[tid] = 0.f;

    // phase 1: per-thread top-4 over 32-element stripe
    float v[4] = {-3.4e38f, -3.4e38f, -3.4e38f, -3.4e38f};
    int id[4] = {0, 0, 0, 0};
    for (int e = tid; e < EN; e += 512) ins4(row[e], e, v, id);

    __shared__ float sv[2048];
    __shared__ int   si[2048];
    __shared__ float sv2[256];
    __shared__ int   si2[256];
    __shared__ int   s_cand[NCAND];
    __shared__ float s_sim[NCAND];
    __shared__ int   s_e[NCAND];

    #pragma unroll
    for (int j = 0; j < 4; j++) { sv[tid * 4 + j] = v[j]; si[tid * 4 + j] = id[j]; }
    __syncthreads();

    if (tid < 64) {
        float v2[4] = {-3.4e38f, -3.4e38f, -3.4e38f, -3.4e38f};
        int id2[4] = {0, 0, 0, 0};
        for (int t = tid * 32; t < tid * 32 + 32; t++) ins4(sv[t], si[t], v2, id2);
        #pragma unroll
        for (int j = 0; j < 4; j++) { sv2[tid * 4 + j] = v2[j]; si2[tid * 4 + j] = id2[j]; }
    }
    __syncthreads();
    if (tid == 0) {
        float v3[16]; int id3[16];
        #pragma unroll
        for (int j = 0; j < 16; j++) { v3[j] = -3.4e38f; id3[j] = 0; }
        for (int t = 0; t < 256; t++) ins16(sv2[t], si2[t], v3, id3);
        #pragma unroll
        for (int j = 0; j < 16; j++) s_cand[j] = id3[j];
    }
    __syncthreads();

    // phase 2: exact fp32 dot + norm per candidate (warp w -> cand w)
    int e = s_cand[w];
    int vv = 2 * (e >> 12) + 1, p = e & (PDIM - 1);
    const float* er = teacher + ((size_t)(b * VDIM + vv) * PDIM + p) * DDIM;
    const float* rr = teacher + ((size_t)(b * VDIM) * PDIM + ref_perm[r]) * DDIM;

    float dot = 0.f, ss = 0.f;
    #pragma unroll
    for (int j = 0; j < 8; j++) {
        int idx = lane * 4 + j * 128;
        float4 x = *(const float4*)(er + idx);
        float4 y = *(const float4*)(rr + idx);
        dot += x.x * y.x + x.y * y.y + x.z * y.z + x.w * y.w;
        ss  += x.x * x.x + x.y * x.y + x.z * x.z + x.w * x.w;
    }
    #pragma unroll
    for (int o = 16; o; o >>= 1) {
        dot += __shfl_xor_sync(0xffffffffu, dot, o);
        ss  += __shfl_xor_sync(0xffffffffu, ss, o);
    }
    if (lane == 0) {
        s_sim[w] = dot / fmaxf(sqrtf(ss), 1e-12f);
        s_e[w] = e;
    }
    __syncthreads();

    // phase 3: exact top-4 of 16; ties -> smaller index (jax.lax.top_k order)
    if (tid == 0) {
        bool used[NCAND];
        #pragma unroll
        for (int j = 0; j < NCAND; j++) used[j] = false;
        #pragma unroll
        for (int j = 0; j < 4; j++) {
            int best = -1;
            float bvv = -3.4e38f; int be = 0x7fffffff;
            for (int t = 0; t < NCAND; t++) {
                if (used[t]) continue;
                if (s_sim[t] > bvv || (s_sim[t] == bvv && s_e[t] < be)) {
                    bvv = s_sim[t]; be = s_e[t]; best = t;
                }
            }
            used[best] = true;
            g_topk[(b * NREF + r) * 4 + j] = s_e[best];
        }
    }
}

// ---------------------------------------------------------------------------
// K3: KL + smooth-L1 losses, 64 threads per row-pair; last block writes out.
// ---------------------------------------------------------------------------
__global__ void __launch_bounds__(256)
k_loss(const float* __restrict__ teacher, const float* __restrict__ student,
       const int* __restrict__ ref_perm, const int* __restrict__ shared_perm,
       float* __restrict__ out) {
    __shared__ float sacc[3];
    __shared__ float r0[4][2], r1[4][2];
    int tid = threadIdx.x;
    if (tid < 3) sacc[tid] = 0.f;

    int grp  = tid >> 6;
    int sub  = tid & 63;
    int w2   = (tid >> 5) & 1;
    int lane = tid & 31;
    int w    = blockIdx.x * 4 + grp;

    const float *pa, *pb, *pc, *pd;
    int target;
    if (w < 1536) {
        target = 0;
        int i = w / 512, rem = w & 511;
        int b = rem >> 8, r = rem & 255;
        int rp = ref_perm[r], sp = shared_perm[r];
        pa = teacher + ((size_t)(b * VDIM) * PDIM + rp) * DDIM;
        pb = teacher + ((size_t)(b * VDIM + c_ST[i]) * PDIM + sp) * DDIM;
        pc = student + ((size_t)(b * 4) * PDIM + rp) * DDIM;
        pd = student + ((size_t)(b * 4 + c_SS[i]) * PDIM + sp) * DDIM;
    } else if (w < 3584) {
        target = 1;
        int t = w - 1536;
        int b = t >> 10, rem = t & 1023;
        int r = rem >> 2, k = rem & 3;
        int rp = ref_perm[r];
        int e = g_topk[((b << 8) + r) * 4 + k];
        int v = 2 * (e >> 12) + 1, p = e & (PDIM - 1);
        pa = teacher + ((size_t)(b * VDIM) * PDIM + rp) * DDIM;
        pc = student + ((size_t)(b * 4) * PDIM + rp) * DDIM;
        pb = pd = teacher + ((size_t)(b * VDIM + v) * PDIM + p) * DDIM;
    } else {
        target = 2;
        int t = w - 3584;
        int i = t >> 11, rem = t & 2047;
        int b = rem >> 10, r = (rem >> 2) & 255, k = rem & 3;
        int sp = shared_perm[r];
        int e = g_topk[((b << 8) + r) * 4 + k];
        int v = 2 * (e >> 12) + 1, p = e & (PDIM - 1);
        pa = teacher + ((size_t)(b * VDIM + c_ST[i]) * PDIM + sp) * DDIM;
        pc = student + ((size_t)(b * 4 + c_SS[i]) * PDIM + sp) * DDIM;
        pb = pd = teacher + ((size_t)(b * VDIM + v) * PDIM + p) * DDIM;
    }

    float dt[16], ds[16];
    bool same = (pb == pd);
    #pragma unroll
    for (int j = 0; j < 4; j++) {
        int idx = sub * 4 + j * 256;
        float4 A  = *(const float4*)(pa + idx);
        float4 Bv = *(const float4*)(pb + idx);
        float4 C  = *(const float4*)(pc + idx);
        float4 Dv = same ? Bv : *(const float4*)(pd + idx);
        dt[4 * j + 0] = A.x - Bv.x; dt[4 * j + 1] = A.y - Bv.y;
        dt[4 * j + 2] = A.z - Bv.z; dt[4 * j + 3] = A.w - Bv.w;
        ds[4 * j + 0] = C.x - Dv.x; ds[4 * j + 1] = C.y - Dv.y;
        ds[4 * j + 2] = C.z - Dv.z; ds[4 * j + 3] = C.w - Dv.w;
    }

    float mt = -3.4e38f, ms = -3.4e38f;
    #pragma unroll
    for (int i = 0; i < 16; i++) { mt = fmaxf(mt, dt[i]); ms = fmaxf(ms, ds[i]); }
    #pragma unroll
    for (int o = 16; o; o >>= 1) {
        mt = fmaxf(mt, __shfl_xor_sync(0xffffffffu, mt, o));
        ms = fmaxf(ms, __shfl_xor_sync(0xffffffffu, ms, o));
    }
    if (lane == 0) { r0[grp][w2] = mt; r1[grp][w2] = ms; }
    __syncthreads();
    mt = fmaxf(r0[grp][0], r0[grp][1]);
    ms = fmaxf(r1[grp][0], r1[grp][1]);

    float st = 0.f, ssum = 0.f;
    #pragma unroll
    for (int i = 0; i < 16; i++) { st += expf(dt[i] - mt); ssum += expf(ds[i] - ms); }
    #pragma unroll
    for (int o = 16; o; o >>= 1) {
        st   += __shfl_xor_sync(0xffffffffu, st, o);
        ssum += __shfl_xor_sync(0xffffffffu, ssum, o);
    }
    __syncthreads();
    if (lane == 0) { r0[grp][w2] = st; r1[grp][w2] = ssum; }
    __syncthreads();
    float lset = mt + logf(r0[grp][0] + r0[grp][1]);
    float lses = ms + logf(r1[grp][0] + r1[grp][1]);

    float acc = 0.f;
    #pragma unroll
    for (int i = 0; i < 16; i++) acc += expf(dt[i] - lset) * (dt[i] - ds[i]);
    #pragma unroll
    for (int o = 16; o; o >>= 1) acc += __shfl_xor_sync(0xffffffffu, acc, o);
    __syncthreads();
    if (lane == 0) r0[grp][w2] = acc;
    __syncthreads();

    if (sub == 0) {
        float kl = (r0[grp][0] + r0[grp][1]) - lset + lses;
        float ax = fabsf(kl);
        float sl = (ax < 0.5f) ? kl * kl : (ax - 0.25f);   // smooth_l1, beta=0.5
        atomicAdd(&sacc[target], sl);
    }
    __syncthreads();
    if (tid < 3) atomicAdd(&g_accum[tid], sacc[tid]);

    // last-arriving block folds the final combine (replaces k_final kernel)
    __syncthreads();
    if (tid == 0) {
        __threadfence();
        unsigned t = atomicAdd(&g_done, 1);
        if (t == gridDim.x - 1) {
            __threadfence();
            out[0] = g_accum[0] * (1.0f / 1536.0f)
                   + g_accum[1] * (1.0f / 2048.0f)
                   + g_accum[2] * (1.0f / 6144.0f);
            g_done = 0;
        }
    }
}

// ---------------------------------------------------------------------------
extern "C" void kernel_launch(void* const* d_in, const int* in_sizes, int n_in,
                              void* d_out, int out_size) {
    const float* teacher     = (const float*)d_in[0];
    const float* student     = (const float*)d_in[1];
    const int*   ref_perm    = (const int*)d_in[2];
    const int*   shared_perm = (const int*)d_in[3];
    float* out = (float*)d_out;

    k_gemm<<<dim3(EN / 128, NREF / 128, BDIM), 512>>>(teacher, ref_perm);
    k_select<<<dim3(NREF, BDIM), 512>>>(teacher, ref_perm);
    k_loss<<<9728 / 4, 256>>>(teacher, student, ref_perm, shared_perm, out);
}

// round 9
// speedup vs baseline: 1.5492x; 1.5492x over previous
#include <cuda_runtime.h>
#include <cuda_bf16.h>
#include <cstdint>

// Problem constants
#define BDIM 2
#define VDIM 8
#define PDIM 4096
#define DDIM 1024
#define NREF 256
#define EN   16384
#define NCAND 8

// Scratch (device globals: allocation-free)
__device__ __nv_bfloat16 g_bbf[BDIM * EN * DDIM];     // 67 MB bf16 extra frames
__device__ __nv_bfloat16 g_abf[BDIM * NREF * DDIM];   // 1 MB bf16 gathered refs
__device__ float g_inv[BDIM * EN];
__device__ float g_sim[BDIM * NREF * EN];             // 33.5 MB
__device__ int   g_topk[BDIM * NREF * 4];
__device__ float g_accum[3];
__device__ unsigned g_done;

__constant__ int c_ST[3] = {2, 4, 6};   // SHARED_TEACHER
__constant__ int c_SS[3] = {1, 2, 3};   // SHARED_STUDENT

__device__ __forceinline__ void ins4(float x, int e, float* v, int* id) {
    if (x <= v[3]) return;
    v[3] = x; id[3] = e;
    #pragma unroll
    for (int j = 3; j >= 1; j--) {
        if (v[j] > v[j - 1]) {
            float tv = v[j]; v[j] = v[j - 1]; v[j - 1] = tv;
            int ti = id[j]; id[j] = id[j - 1]; id[j - 1] = ti;
        }
    }
}

__device__ __forceinline__ void ins8(float x, int e, float* v, int* id) {
    if (x <= v[7]) return;
    v[7] = x; id[7] = e;
    #pragma unroll
    for (int j = 7; j >= 1; j--) {
        if (v[j] > v[j - 1]) {
            float tv = v[j]; v[j] = v[j - 1]; v[j - 1] = tv;
            int ti = id[j]; id[j] = id[j - 1]; id[j - 1] = ti;
        }
    }
}

// ---------------------------------------------------------------------------
// K0: one-pass f32->bf16 convert (+ exact f32 inverse norms for extra rows)
//   blocks [0, B*EN):            extra-frame rows -> g_bbf + g_inv
//   blocks [B*EN, B*EN+B*NREF):  gathered ref rows -> g_abf
// ---------------------------------------------------------------------------
__global__ void __launch_bounds__(128)
k_convert(const float* __restrict__ teacher, const int* __restrict__ ref_perm) {
    const int id  = blockIdx.x;
    const int tid = threadIdx.x;

    const float* src;
    __nv_bfloat16* dst;
    bool donorm;
    int nidx = 0;
    if (id < BDIM * EN) {
        int b = id >> 14, e = id & (EN - 1);
        int v = 2 * (e >> 12) + 1, p = e & (PDIM - 1);
        src = teacher + ((size_t)(b * VDIM + v) * PDIM + p) * DDIM;
        dst = g_bbf + (size_t)id * DDIM;
        donorm = true; nidx = id;
    } else {
        int t = id - BDIM * EN;
        int b = t >> 8, r = t & 255;
        src = teacher + ((size_t)(b * VDIM) * PDIM + ref_perm[r]) * DDIM;
        dst = g_abf + (size_t)t * DDIM;
        donorm = false;
    }

    float4 x0 = ((const float4*)src)[tid * 2];
    float4 x1 = ((const float4*)src)[tid * 2 + 1];
    __nv_bfloat162 h0, h1, h2, h3;
    h0.x = __float2bfloat16(x0.x); h0.y = __float2bfloat16(x0.y);
    h1.x = __float2bfloat16(x0.z); h1.y = __float2bfloat16(x0.w);
    h2.x = __float2bfloat16(x1.x); h2.y = __float2bfloat16(x1.y);
    h3.x = __float2bfloat16(x1.z); h3.y = __float2bfloat16(x1.w);
    uint4 pk;
    pk.x = *(uint32_t*)&h0; pk.y = *(uint32_t*)&h1;
    pk.z = *(uint32_t*)&h2; pk.w = *(uint32_t*)&h3;
    ((uint4*)dst)[tid] = pk;

    if (donorm) {
        float ss = x0.x * x0.x + x0.y * x0.y + x0.z * x0.z + x0.w * x0.w
                 + x1.x * x1.x + x1.y * x1.y + x1.z * x1.z + x1.w * x1.w;
        #pragma unroll
        for (int o = 16; o; o >>= 1) ss += __shfl_xor_sync(0xffffffffu, ss, o);
        __shared__ float sh[4];
        if ((tid & 31) == 0) sh[tid >> 5] = ss;
        __syncthreads();
        if (tid == 0) {
            float t = sh[0] + sh[1] + sh[2] + sh[3];
            g_inv[nidx] = 1.0f / fmaxf(sqrtf(t), 1e-12f);
        }
    }
}

// ---------------------------------------------------------------------------
// K1: pure bf16 GEMM, cp.async 3-stage pipeline, 128x128 CTA tile, BK=32,
//     256 threads, 8 warps, warp tile 64x32. No cvt / no LDG-reg chains.
// ---------------------------------------------------------------------------
#define KSTEP 32
#define NKT   (DDIM / KSTEP)     // 32
#define STAGES 3
#define AROWB 80                 // 64 data bytes + 16 pad per k-row
#define STAGE_BYTES 20480        // A 10240 + B 10240
#define GEMM_SMEM (STAGES * STAGE_BYTES)   // 61440

__device__ __forceinline__ void cp_async16(uint32_t dst, const void* src) {
    asm volatile("cp.async.cg.shared.global [%0], [%1], 16;" :: "r"(dst), "l"(src));
}

__global__ void __launch_bounds__(256, 2)
k_gemm() {
    extern __shared__ __align__(16) uint8_t smem[];
    __shared__ float s_inv[128];

    const int b     = blockIdx.z;
    const int rbase = blockIdx.y * 128;
    const int ebase = blockIdx.x * 128;
    const int tid   = threadIdx.x;
    const int lane  = tid & 31;
    const int wid   = tid >> 5;
    const int wm    = (wid >> 2) * 64;
    const int wn    = (wid & 3) * 32;
    const uint32_t sbase = (uint32_t)__cvta_generic_to_shared(smem);

    // loaders: thread t -> row t>>1, 32-byte k-chunk (t&1)
    const int lrow = tid >> 1;
    const int lkB  = (tid & 1) * 32;

    const char* aG = (const char*)(g_abf + ((size_t)(b * NREF + rbase + lrow)) * DDIM) + lkB;
    const char* bG = (const char*)(g_bbf + ((size_t)(b * EN   + ebase + lrow)) * DDIM) + lkB;
    const uint32_t aS = sbase + lrow * AROWB + lkB;
    const uint32_t bS = aS + 10240;

    float acc[4][4][4];
    #pragma unroll
    for (int i = 0; i < 4; i++)
        #pragma unroll
        for (int j = 0; j < 4; j++)
            #pragma unroll
            for (int k = 0; k < 4; k++) acc[i][j][k] = 0.f;

    // ldmatrix lane addressing (byte offsets within a stage)
    const int xr = (lane & 7) + ((lane >> 3) & 1) * 8;
    const int xk = (lane >> 4) * 16;                 // byte offset of 8-half group
    uint32_t a_off[4], b_off[2];
    #pragma unroll
    for (int mi = 0; mi < 4; mi++)
        a_off[mi] = (uint32_t)((wm + mi * 16 + xr) * AROWB + xk);
    #pragma unroll
    for (int nj = 0; nj < 2; nj++)
        b_off[nj] = 10240u + (uint32_t)((wn + nj * 16 + xr) * AROWB + xk);

    // prologue: issue stages 0..STAGES-2
    #pragma unroll
    for (int s = 0; s < STAGES - 1; s++) {
        cp_async16(aS + s * STAGE_BYTES,      aG + s * 64);
        cp_async16(aS + s * STAGE_BYTES + 16, aG + s * 64 + 16);
        cp_async16(bS + s * STAGE_BYTES,      bG + s * 64);
        cp_async16(bS + s * STAGE_BYTES + 16, bG + s * 64 + 16);
        asm volatile("cp.async.commit_group;");
    }

    for (int kt = 0; kt < NKT; kt++) {
        asm volatile("cp.async.wait_group %0;" :: "n"(STAGES - 2));
        __syncthreads();

        // issue the stage that was consumed in iteration kt-1
        int wst = kt + STAGES - 1;
        if (wst < NKT) {
            int st = wst % STAGES;
            cp_async16(aS + st * STAGE_BYTES,      aG + wst * 64);
            cp_async16(aS + st * STAGE_BYTES + 16, aG + wst * 64 + 16);
            cp_async16(bS + st * STAGE_BYTES,      bG + wst * 64);
            cp_async16(bS + st * STAGE_BYTES + 16, bG + wst * 64 + 16);
        }
        asm volatile("cp.async.commit_group;");

        const uint32_t stg = (kt % STAGES) * STAGE_BYTES;
        #pragma unroll
        for (int ks = 0; ks < 64; ks += 32) {      // two 16-half k-steps (bytes)
            uint32_t af[4][4], bf[2][4];
            #pragma unroll
            for (int mi = 0; mi < 4; mi++) {
                asm volatile("ldmatrix.sync.aligned.m8n8.x4.shared.b16 {%0,%1,%2,%3}, [%4];"
                    : "=r"(af[mi][0]), "=r"(af[mi][1]), "=r"(af[mi][2]), "=r"(af[mi][3])
                    : "r"(sbase + stg + a_off[mi] + ks));
            }
            #pragma unroll
            for (int nj = 0; nj < 2; nj++) {
                asm volatile("ldmatrix.sync.aligned.m8n8.x4.shared.b16 {%0,%1,%2,%3}, [%4];"
                    : "=r"(bf[nj][0]), "=r"(bf[nj][1]), "=r"(bf[nj][2]), "=r"(bf[nj][3])
                    : "r"(sbase + stg + b_off[nj] + ks));
            }
            #pragma unroll
            for (int mi = 0; mi < 4; mi++) {
                #pragma unroll
                for (int nj = 0; nj < 4; nj++) {
                    uint32_t bb0 = bf[nj >> 1][nj & 1];
                    uint32_t bb1 = bf[nj >> 1][(nj & 1) + 2];
                    asm volatile(
                        "mma.sync.aligned.m16n8k16.row.col.f32.bf16.bf16.f32 "
                        "{%0,%1,%2,%3}, {%4,%5,%6,%7}, {%8,%9}, {%0,%1,%2,%3};"
                        : "+f"(acc[mi][nj][0]), "+f"(acc[mi][nj][1]),
                          "+f"(acc[mi][nj][2]), "+f"(acc[mi][nj][3])
                        : "r"(af[mi][0]), "r"(af[mi][1]), "r"(af[mi][2]), "r"(af[mi][3]),
                          "r"(bb0), "r"(bb1));
                }
            }
        }
    }

    // inverse norms for this column tile (exact, precomputed from f32)
    __syncthreads();
    if (tid < 128) s_inv[tid] = g_inv[b * EN + ebase + tid];
    __syncthreads();

    // epilogue: scale by inv_norm[e], write sim
    #pragma unroll
    for (int mi = 0; mi < 4; mi++) {
        int r = rbase + wm + mi * 16 + (lane >> 2);
        float* orow = g_sim + ((size_t)(b * NREF + r)) * EN + ebase;
        #pragma unroll
        for (int nj = 0; nj < 4; nj++) {
            int c = wn + nj * 8 + (lane & 3) * 2;
            float2 w0 = make_float2(acc[mi][nj][0] * s_inv[c], acc[mi][nj][1] * s_inv[c + 1]);
            float2 w1 = make_float2(acc[mi][nj][2] * s_inv[c], acc[mi][nj][3] * s_inv[c + 1]);
            *(float2*)(orow + c)          = w0;
            *(float2*)(orow + 8 * EN + c) = w1;
        }
    }
}

// ---------------------------------------------------------------------------
// K2: per (b,r): top-8 candidates from bf16 sims, then exact fp32 re-rank
//     -> exact top-4 indices (R7-proven).
// ---------------------------------------------------------------------------
__global__ void __launch_bounds__(256)
k_select(const float* __restrict__ teacher, const int* __restrict__ ref_perm) {
    int r = blockIdx.x, b = blockIdx.y, tid = threadIdx.x;
    int w = tid >> 5, lane = tid & 31;
    const float* row = g_sim + ((size_t)(b * NREF + r)) * EN;

    if (r == 0 && b == 0 && tid < 3) g_accum[tid] = 0.f;

    float v[4] = {-3.4e38f, -3.4e38f, -3.4e38f, -3.4e38f};
    int id[4] = {0, 0, 0, 0};
    for (int e = tid; e < EN; e += 256) ins4(row[e], e, v, id);

    __shared__ float sv[1024];
    __shared__ int   si[1024];
    __shared__ int   s_cand[NCAND];
    __shared__ float s_sim[NCAND];
    __shared__ int   s_e[NCAND];

    #pragma unroll
    for (int j = 0; j < 4; j++) { sv[tid * 4 + j] = v[j]; si[tid * 4 + j] = id[j]; }
    __syncthreads();

    if (tid < 32) {
        float v2[4] = {-3.4e38f, -3.4e38f, -3.4e38f, -3.4e38f};
        int id2[4] = {0, 0, 0, 0};
        for (int t = tid * 32; t < tid * 32 + 32; t++) ins4(sv[t], si[t], v2, id2);
        __syncwarp();
        #pragma unroll
        for (int j = 0; j < 4; j++) { sv[tid * 4 + j] = v2[j]; si[tid * 4 + j] = id2[j]; }
        __syncwarp();
        if (tid == 0) {
            float v3[8]; int id3[8];
            #pragma unroll
            for (int j = 0; j < 8; j++) { v3[j] = -3.4e38f; id3[j] = 0; }
            for (int t = 0; t < 128; t++) ins8(sv[t], si[t], v3, id3);
            #pragma unroll
            for (int j = 0; j < 8; j++) s_cand[j] = id3[j];
        }
    }
    __syncthreads();

    int e = s_cand[w];
    int vv = 2 * (e >> 12) + 1, p = e & (PDIM - 1);
    const float* er = teacher + ((size_t)(b * VDIM + vv) * PDIM + p) * DDIM;
    const float* rr = teacher + ((size_t)(b * VDIM) * PDIM + ref_perm[r]) * DDIM;

    float dot = 0.f, ss = 0.f;
    #pragma unroll
    for (int j = 0; j < 8; j++) {
        int idx = lane * 4 + j * 128;
        float4 x = *(const float4*)(er + idx);
        float4 y = *(const float4*)(rr + idx);
        dot += x.x * y.x + x.y * y.y + x.z * y.z + x.w * y.w;
        ss  += x.x * x.x + x.y * x.y + x.z * x.z + x.w * x.w;
    }
    #pragma unroll
    for (int o = 16; o; o >>= 1) {
        dot += __shfl_xor_sync(0xffffffffu, dot, o);
        ss  += __shfl_xor_sync(0xffffffffu, ss, o);
    }
    if (lane == 0) {
        s_sim[w] = dot / fmaxf(sqrtf(ss), 1e-12f);
        s_e[w] = e;
    }
    __syncthreads();

    if (tid == 0) {
        bool used[NCAND] = {false, false, false, false, false, false, false, false};
        #pragma unroll
        for (int j = 0; j < 4; j++) {
            int best = -1;
            float bvv = -3.4e38f; int be = 0x7fffffff;
            for (int t = 0; t < NCAND; t++) {
                if (used[t]) continue;
                if (s_sim[t] > bvv || (s_sim[t] == bvv && s_e[t] < be)) {
                    bvv = s_sim[t]; be = s_e[t]; best = t;
                }
            }
            used[best] = true;
            g_topk[(b * NREF + r) * 4 + j] = s_e[best];
        }
    }
}

// ---------------------------------------------------------------------------
// K3: KL + smooth-L1 losses, 64 threads per row-pair; last block writes out.
// ---------------------------------------------------------------------------
__global__ void __launch_bounds__(256)
k_loss(const float* __restrict__ teacher, const float* __restrict__ student,
       const int* __restrict__ ref_perm, const int* __restrict__ shared_perm,
       float* __restrict__ out) {
    __shared__ float sacc[3];
    __shared__ float r0[4][2], r1[4][2];
    int tid = threadIdx.x;
    if (tid < 3) sacc[tid] = 0.f;

    int grp  = tid >> 6;
    int sub  = tid & 63;
    int w2   = (tid >> 5) & 1;
    int lane = tid & 31;
    int w    = blockIdx.x * 4 + grp;

    const float *pa, *pb, *pc, *pd;
    int target;
    if (w < 1536) {
        target = 0;
        int i = w / 512, rem = w & 511;
        int b = rem >> 8, r = rem & 255;
        int rp = ref_perm[r], sp = shared_perm[r];
        pa = teacher + ((size_t)(b * VDIM) * PDIM + rp) * DDIM;
        pb = teacher + ((size_t)(b * VDIM + c_ST[i]) * PDIM + sp) * DDIM;
        pc = student + ((size_t)(b * 4) * PDIM + rp) * DDIM;
        pd = student + ((size_t)(b * 4 + c_SS[i]) * PDIM + sp) * DDIM;
    } else if (w < 3584) {
        target = 1;
        int t = w - 1536;
        int b = t >> 10, rem = t & 1023;
        int r = rem >> 2, k = rem & 3;
        int rp = ref_perm[r];
        int e = g_topk[((b << 8) + r) * 4 + k];
        int v = 2 * (e >> 12) + 1, p = e & (PDIM - 1);
        pa = teacher + ((size_t)(b * VDIM) * PDIM + rp) * DDIM;
        pc = student + ((size_t)(b * 4) * PDIM + rp) * DDIM;
        pb = pd = teacher + ((size_t)(b * VDIM + v) * PDIM + p) * DDIM;
    } else {
        target = 2;
        int t = w - 3584;
        int i = t >> 11, rem = t & 2047;
        int b = rem >> 10, r = (rem >> 2) & 255, k = rem & 3;
        int sp = shared_perm[r];
        int e = g_topk[((b << 8) + r) * 4 + k];
        int v = 2 * (e >> 12) + 1, p = e & (PDIM - 1);
        pa = teacher + ((size_t)(b * VDIM + c_ST[i]) * PDIM + sp) * DDIM;
        pc = student + ((size_t)(b * 4 + c_SS[i]) * PDIM + sp) * DDIM;
        pb = pd = teacher + ((size_t)(b * VDIM + v) * PDIM + p) * DDIM;
    }

    float dt[16], ds[16];
    bool same = (pb == pd);
    #pragma unroll
    for (int j = 0; j < 4; j++) {
        int idx = sub * 4 + j * 256;
        float4 A  = *(const float4*)(pa + idx);
        float4 Bv = *(const float4*)(pb + idx);
        float4 C  = *(const float4*)(pc + idx);
        float4 Dv = same ? Bv : *(const float4*)(pd + idx);
        dt[4 * j + 0] = A.x - Bv.x; dt[4 * j + 1] = A.y - Bv.y;
        dt[4 * j + 2] = A.z - Bv.z; dt[4 * j + 3] = A.w - Bv.w;
        ds[4 * j + 0] = C.x - Dv.x; ds[4 * j + 1] = C.y - Dv.y;
        ds[4 * j + 2] = C.z - Dv.z; ds[4 * j + 3] = C.w - Dv.w;
    }

    float mt = -3.4e38f, ms = -3.4e38f;
    #pragma unroll
    for (int i = 0; i < 16; i++) { mt = fmaxf(mt, dt[i]); ms = fmaxf(ms, ds[i]); }
    #pragma unroll
    for (int o = 16; o; o >>= 1) {
        mt = fmaxf(mt, __shfl_xor_sync(0xffffffffu, mt, o));
        ms = fmaxf(ms, __shfl_xor_sync(0xffffffffu, ms, o));
    }
    if (lane == 0) { r0[grp][w2] = mt; r1[grp][w2] = ms; }
    __syncthreads();
    mt = fmaxf(r0[grp][0], r0[grp][1]);
    ms = fmaxf(r1[grp][0], r1[grp][1]);

    float st = 0.f, ssum = 0.f;
    #pragma unroll
    for (int i = 0; i < 16; i++) { st += expf(dt[i] - mt); ssum += expf(ds[i] - ms); }
    #pragma unroll
    for (int o = 16; o; o >>= 1) {
        st   += __shfl_xor_sync(0xffffffffu, st, o);
        ssum += __shfl_xor_sync(0xffffffffu, ssum, o);
    }
    __syncthreads();
    if (lane == 0) { r0[grp][w2] = st; r1[grp][w2] = ssum; }
    __syncthreads();
    float lset = mt + logf(r0[grp][0] + r0[grp][1]);
    float lses = ms + logf(r1[grp][0] + r1[grp][1]);

    float acc = 0.f;
    #pragma unroll
    for (int i = 0; i < 16; i++) acc += expf(dt[i] - lset) * (dt[i] - ds[i]);
    #pragma unroll
    for (int o = 16; o; o >>= 1) acc += __shfl_xor_sync(0xffffffffu, acc, o);
    __syncthreads();
    if (lane == 0) r0[grp][w2] = acc;
    __syncthreads();

    if (sub == 0) {
        float kl = (r0[grp][0] + r0[grp][1]) - lset + lses;
        float ax = fabsf(kl);
        float sl = (ax < 0.5f) ? kl * kl : (ax - 0.25f);   // smooth_l1, beta=0.5
        atomicAdd(&sacc[target], sl);
    }
    __syncthreads();
    if (tid < 3) atomicAdd(&g_accum[tid], sacc[tid]);

    // last-arriving block folds the final combine
    __syncthreads();
    if (tid == 0) {
        __threadfence();
        unsigned t = atomicAdd(&g_done, 1);
        if (t == gridDim.x - 1) {
            __threadfence();
            out[0] = g_accum[0] * (1.0f / 1536.0f)
                   + g_accum[1] * (1.0f / 2048.0f)
                   + g_accum[2] * (1.0f / 6144.0f);
            g_done = 0;
        }
    }
}

// ---------------------------------------------------------------------------
extern "C" void kernel_launch(void* const* d_in, const int* in_sizes, int n_in,
                              void* d_out, int out_size) {
    const float* teacher     = (const float*)d_in[0];
    const float* student     = (const float*)d_in[1];
    const int*   ref_perm    = (const int*)d_in[2];
    const int*   shared_perm = (const int*)d_in[3];
    float* out = (float*)d_out;

    cudaFuncSetAttribute(k_gemm, cudaFuncAttributeMaxDynamicSharedMemorySize, GEMM_SMEM);

    k_convert<<<BDIM * EN + BDIM * NREF, 128>>>(teacher, ref_perm);
    k_gemm<<<dim3(EN / 128, NREF / 128, BDIM), 256, GEMM_SMEM>>>();
    k_select<<<dim3(NREF, BDIM), 256>>>(teacher, ref_perm);
    k_loss<<<9728 / 4, 256>>>(teacher, student, ref_perm, shared_perm, out);
}